// round 15
// baseline (speedup 1.0000x reference)
#include <cuda_runtime.h>
#include <cuda_fp16.h>
#include <math.h>
#include <stdint.h>

// Problem constants
#define BATCH 4
#define CCH   192
#define NPIX  65536
#define HEADS 8
#define CH    24
#define GSPLIT 74
#define NCHUNK 1024            // total 64-px chunks per (b) strip

// ---------------- device scratch (static, no allocation) ----------------
__device__ float g_Spart[(size_t)BATCH * 6 * GSPLIT * 4096];
__device__ float g_S[BATCH * CCH * CCH];
__device__ float g_T[BATCH * 2 * CCH * CCH];
__device__ float g_attn[BATCH * HEADS * CH * CH];
__device__ __align__(16) __half g_Ph[BATCH * CCH * CCH];
__device__ __align__(16) __half g_Xh[(size_t)BATCH * CCH * NPIX];

// ---------------- helpers ----------------
__device__ __forceinline__ unsigned pkh(float a, float b) {
    __half2 h = __floats2half2_rn(a, b);
    return *reinterpret_cast<unsigned*>(&h);
}
__device__ __forceinline__ uint32_t s2u(const void* p) {
    uint32_t a;
    asm("{.reg .u64 t; cvta.to.shared.u64 t, %1; cvt.u32.u64 %0, t;}" : "=r"(a) : "l"(p));
    return a;
}
__device__ __forceinline__ void mma_h(float* d, const unsigned* a,
                                      unsigned b0, unsigned b1) {
    asm volatile(
        "mma.sync.aligned.m16n8k16.row.col.f32.f16.f16.f32 "
        "{%0,%1,%2,%3}, {%4,%5,%6,%7}, {%8,%9}, {%0,%1,%2,%3};"
        : "+f"(d[0]), "+f"(d[1]), "+f"(d[2]), "+f"(d[3])
        : "r"(a[0]), "r"(a[1]), "r"(a[2]), "r"(a[3]), "r"(b0), "r"(b1));
}
__device__ __forceinline__ void ldm_x4(unsigned* r, uint32_t a) {
    asm volatile("ldmatrix.sync.aligned.m8n8.x4.shared.b16 {%0,%1,%2,%3}, [%4];"
                 : "=r"(r[0]), "=r"(r[1]), "=r"(r[2]), "=r"(r[3]) : "r"(a));
}
__device__ __forceinline__ void ldm_x4_t(unsigned* r, uint32_t a) {
    asm volatile("ldmatrix.sync.aligned.m8n8.x4.trans.shared.b16 {%0,%1,%2,%3}, [%4];"
                 : "=r"(r[0]), "=r"(r[1]), "=r"(r[2]), "=r"(r[3]) : "r"(a));
}
#define CPA16(dst, src) asm volatile("cp.async.cg.shared.global [%0], [%1], 16;" :: "r"(dst), "l"(src))
#define CPCOMMIT()      asm volatile("cp.async.commit_group;")
#define CPWAIT(n)       asm volatile("cp.async.wait_group %0;" :: "n"(n))

__device__ __forceinline__ void tile_pair(int tp, int& ti, int& tj) {
    ti = (tp < 3) ? 0 : ((tp < 5) ? 1 : 2);
    tj = (tp < 3) ? tp : ((tp < 5) ? tp - 2 : 2);
}

// =====================================================================
// Kernel 1: FUSED convert + partial Gram. grid (GSPLIT, BATCH), 256 thr.
// 296 CTAs = one full 2-CTA/SM wave on 148 SMs.
// =====================================================================
#define GF_SMEM 107520

__global__ __launch_bounds__(256) void gram_f(const float* __restrict__ X) {
    extern __shared__ char dsm[];
    float* F = (float*)dsm;
    __half* Hgen = (__half*)(dsm + 52224);
    const uint32_t sF = s2u(dsm);
    const uint32_t sH = sF + 52224;

    const int split = blockIdx.x, b = blockIdx.y;
    const int c0 = (split * NCHUNK) / GSPLIT;
    const int nch = ((split + 1) * NCHUNK) / GSPLIT - c0;
    const int t = threadIdx.x, lane = t & 31, wid = t >> 5;
    const int g = lane >> 2, tg = lane & 3;
    const int lr = lane & 15, lu = lane >> 4;

    int abase[3], bbase[3];
#pragma unroll
    for (int j = 0; j < 3; j++) {
        const int wt = wid + j * 8;
        const int tp = wt >> 2, quad = wt & 3;
        int ti, tj; tile_pair(tp, ti, tj);
        abase[j] = ti * 64 + (quad >> 1) * 32;
        bbase[j] = tj * 64 + (quad & 1) * 32;
    }

    const float* Xs0 = X + ((size_t)b * CCH) * NPIX + c0 * 64;
    __half* Xh0 = g_Xh + ((size_t)b * CCH) * NPIX + c0 * 64;

    float acc[3][2][4][4];
#pragma unroll
    for (int j = 0; j < 3; j++)
#pragma unroll
        for (int mi = 0; mi < 2; mi++)
#pragma unroll
            for (int nj = 0; nj < 4; nj++)
#pragma unroll
                for (int u = 0; u < 4; u++) acc[j][mi][nj][u] = 0.f;

#pragma unroll
    for (int i = 0; i < 12; i++) {
        const int unit = t + i * 256;
        const int row = unit >> 4, u16 = unit & 15;
        CPA16(sF + row * 272 + u16 * 16, Xs0 + (size_t)row * NPIX + u16 * 4);
    }
    CPCOMMIT();

#pragma unroll 1
    for (int ch = 0; ch < nch; ch++) {
        CPWAIT(0);
        __syncthreads();

        __half* hgen = Hgen + (ch & 1) * 13824;
        const uint32_t hb = sH + (ch & 1) * 27648;
#pragma unroll
        for (int i = 0; i < 6; i++) {
            const int unit = t + i * 256;
            const int row = unit >> 3, cg = unit & 7;
            float4 v0 = *(const float4*)((const char*)F + row * 272 + cg * 32);
            float4 v1 = *(const float4*)((const char*)F + row * 272 + cg * 32 + 16);
            uint4 o = make_uint4(pkh(v0.x, v0.y), pkh(v0.z, v0.w),
                                 pkh(v1.x, v1.y), pkh(v1.z, v1.w));
            *(uint4*)(hgen + row * 72 + cg * 8) = o;
            *(uint4*)(Xh0 + (size_t)row * NPIX + ch * 64 + cg * 8) = o;
        }
        __syncthreads();

        if (ch + 1 < nch) {
#pragma unroll
            for (int i = 0; i < 12; i++) {
                const int unit = t + i * 256;
                const int row = unit >> 4, u16 = unit & 15;
                CPA16(sF + row * 272 + u16 * 16,
                      Xs0 + (size_t)row * NPIX + (ch + 1) * 64 + u16 * 4);
            }
            CPCOMMIT();
        }

#pragma unroll
        for (int ks = 0; ks < 4; ks++) {
            const uint32_t col = (ks * 2 + lu) * 16;
#pragma unroll
            for (int j = 0; j < 3; j++) {
                unsigned af[2][4], bf[4][2], tmp[4];
#pragma unroll
                for (int mi = 0; mi < 2; mi++)
                    ldm_x4(af[mi], hb + (abase[j] + mi * 16 + lr) * 144 + col);
#pragma unroll
                for (int nj2 = 0; nj2 < 2; nj2++) {
                    ldm_x4(tmp, hb + (bbase[j] + nj2 * 16 + lr) * 144 + col);
                    bf[nj2 * 2][0] = tmp[0]; bf[nj2 * 2][1] = tmp[2];
                    bf[nj2 * 2 + 1][0] = tmp[1]; bf[nj2 * 2 + 1][1] = tmp[3];
                }
#pragma unroll
                for (int mi = 0; mi < 2; mi++)
#pragma unroll
                    for (int nj = 0; nj < 4; nj++)
                        mma_h(acc[j][mi][nj], af[mi], bf[nj][0], bf[nj][1]);
            }
        }
    }

#pragma unroll
    for (int j = 0; j < 3; j++) {
        const int wt = wid + j * 8;
        const int tp = wt >> 2, quad = wt & 3;
        const int qm = (quad >> 1) * 32, qn = (quad & 1) * 32;
        float* out = g_Spart + ((size_t)((b * 6 + tp) * GSPLIT + split) << 12);
#pragma unroll
        for (int mi = 0; mi < 2; mi++)
#pragma unroll
            for (int nj = 0; nj < 4; nj++) {
                const int m0 = qm + mi * 16 + g;
                const int nc = qn + nj * 8 + 2 * tg;
                *(float2*)&out[m0 * 64 + nc]       = make_float2(acc[j][mi][nj][0], acc[j][mi][nj][1]);
                *(float2*)&out[(m0 + 8) * 64 + nc] = make_float2(acc[j][mi][nj][2], acc[j][mi][nj][3]);
            }
    }
}

// =====================================================================
// Kernel 2: split reduction + mirror. grid(192), 256 thr.
// =====================================================================
__global__ __launch_bounds__(256) void gram_reduce6() {
    const int q = blockIdx.x & 7, blk = blockIdx.x >> 3;
    const int b = blk / 6, tp = blk % 6;
    int ti, tj; tile_pair(tp, ti, tj);
    const float* base = g_Spart + ((size_t)(b * 6 + tp) * GSPLIT << 12);
    for (int idx = q * 512 + threadIdx.x; idx < (q + 1) * 512; idx += 256) {
        float s = 0.f;
#pragma unroll
        for (int sp = 0; sp < GSPLIT; sp++) s += base[((size_t)sp << 12) + idx];
        const int i = idx >> 6, j = idx & 63;
        g_S[b * CCH * CCH + (ti * 64 + i) * CCH + (tj * 64 + j)] = s;
        if (ti != tj)
            g_S[b * CCH * CCH + (tj * 64 + j) * CCH + (ti * 64 + i)] = s;
    }
}

// =====================================================================
// Kernel 3a: T = W_qk @ S. grid (12, 3, BATCH), 256 thr, 32x64 tiles.
// =====================================================================
__global__ __launch_bounds__(256) void qk_kernel(const float* __restrict__ wqkv) {
    const int r0 = blockIdx.x * 32, m0 = blockIdx.y * 64, b = blockIdx.z;
    __shared__ float Ws[32][36], Ss[32][68];
    const int t = threadIdx.x, tx = t & 15, ty = t >> 4;
    const float* Sb = g_S + b * CCH * CCH;

    float acc[2][4];
#pragma unroll
    for (int i = 0; i < 2; i++)
#pragma unroll
        for (int j = 0; j < 4; j++) acc[i][j] = 0.f;

#pragma unroll 1
    for (int k0 = 0; k0 < CCH; k0 += 32) {
        {
            const int r = t >> 3, c4 = (t & 7) << 2;
            *(float4*)&Ws[r][c4] = *(const float4*)(wqkv + (r0 + r) * CCH + k0 + c4);
        }
#pragma unroll
        for (int i = 0; i < 2; i++) {
            const int idx = t + i * 256;
            const int kk = idx >> 4, m4 = (idx & 15) << 2;
            *(float4*)&Ss[kk][m4] = *(const float4*)(Sb + (k0 + kk) * CCH + m0 + m4);
        }
        __syncthreads();
#pragma unroll
        for (int kk = 0; kk < 32; kk++) {
            float av0 = Ws[ty * 2][kk], av1 = Ws[ty * 2 + 1][kk];
            float4 b4 = *(const float4*)&Ss[kk][tx * 4];
            acc[0][0] = fmaf(av0, b4.x, acc[0][0]);
            acc[0][1] = fmaf(av0, b4.y, acc[0][1]);
            acc[0][2] = fmaf(av0, b4.z, acc[0][2]);
            acc[0][3] = fmaf(av0, b4.w, acc[0][3]);
            acc[1][0] = fmaf(av1, b4.x, acc[1][0]);
            acc[1][1] = fmaf(av1, b4.y, acc[1][1]);
            acc[1][2] = fmaf(av1, b4.z, acc[1][2]);
            acc[1][3] = fmaf(av1, b4.w, acc[1][3]);
        }
        __syncthreads();
    }
#pragma unroll
    for (int i = 0; i < 2; i++)
        *(float4*)&g_T[((size_t)b * 384 + r0 + ty * 2 + i) * CCH + m0 + tx * 4] =
            make_float4(acc[i][0], acc[i][1], acc[i][2], acc[i][3]);
}

// =====================================================================
// Kernel 3b: attn5 — one thread per G element (576 dots of len 192),
// norms on threads 576..623, warp-per-row softmax. grid (8,4), 768 thr.
// Stride 197 (5 mod 32) -> the 24 distinct rows hit distinct banks.
// =====================================================================
#define SD5 197
#define ATTN5_SMEM ((4 * 24 * SD5 + 576 + 48) * sizeof(float))

__global__ __launch_bounds__(768) void attn5(const float* __restrict__ wqkv,
                                             const float* __restrict__ temp) {
    const int h = blockIdx.x, b = blockIdx.y;
    extern __shared__ float smf[];
    float* T1s = smf;
    float* T2s = T1s + 24 * SD5;
    float* Wqs = T2s + 24 * SD5;
    float* Wks = Wqs + 24 * SD5;
    float* Gs  = Wks + 24 * SD5;
    float* nqv = Gs + 576;
    float* nkv = nqv + 24;
    const int t = threadIdx.x, lane = t & 31, wrp = t >> 5;

    for (int idx = t; idx < 24 * 192; idx += 768) {
        const int c = idx / 192, m = idx % 192;
        T1s[c * SD5 + m] = g_T[((size_t)b * 384 + h * CH + c) * CCH + m];
        T2s[c * SD5 + m] = g_T[((size_t)b * 384 + 192 + h * CH + c) * CCH + m];
        Wqs[c * SD5 + m] = wqkv[(h * CH + c) * CCH + m];
        Wks[c * SD5 + m] = wqkv[(CCH + h * CH + c) * CCH + m];
    }
    __syncthreads();

    if (t < 576) {
        const int c = t / 24, d = t % 24;
        const float* a = T1s + c * SD5;
        const float* w = Wks + d * SD5;
        float s = 0.f;
#pragma unroll 8
        for (int k = 0; k < CCH; k++) s = fmaf(a[k], w[k], s);
        Gs[t] = s;
    } else if (t < 600) {
        const int c = t - 576;
        const float* a = T1s + c * SD5;
        const float* w = Wqs + c * SD5;
        float s = 0.f;
#pragma unroll 8
        for (int k = 0; k < CCH; k++) s = fmaf(a[k], w[k], s);
        nqv[c] = fmaxf(sqrtf(s), 1e-12f);
    } else if (t < 624) {
        const int c = t - 600;
        const float* a = T2s + c * SD5;
        const float* w = Wks + c * SD5;
        float s = 0.f;
#pragma unroll 8
        for (int k = 0; k < CCH; k++) s = fmaf(a[k], w[k], s);
        nkv[c] = fmaxf(sqrtf(s), 1e-12f);
    }
    __syncthreads();

    // softmax: warp c handles row c (lane d holds column d)
    if (wrp < 24) {
        const int c = wrp;
        const float tp = temp[h];
        const float nq = nqv[c];
        const float nk = (lane < 24) ? nkv[lane] : 1.f;
        float l = (lane < 24) ? Gs[c * 24 + lane] * tp / (nq * nk) : -1e30f;
        float mx = l;
#pragma unroll
        for (int o = 16; o; o >>= 1) mx = fmaxf(mx, __shfl_xor_sync(0xFFFFFFFFu, mx, o));
        const float e = (lane < 24) ? expf(l - mx) : 0.f;
        float ssum = e;
#pragma unroll
        for (int o = 16; o; o >>= 1) ssum += __shfl_xor_sync(0xFFFFFFFFu, ssum, o);
        if (lane < 24)
            g_attn[((b * HEADS + h) * CH + c) * CH + lane] = e / ssum;
    }
}

// =====================================================================
// Kernel 4: FUSED  M = W_out @ blockdiag(attn);  P = M @ W_v  -> fp16.
// grid (6, 6, BATCH), 256 threads.
// =====================================================================
__global__ __launch_bounds__(256) void mp_kernel(const float* __restrict__ wout,
                                                 const float* __restrict__ wqkv) {
    const int b = blockIdx.z;
    const int i0 = blockIdx.y * 32, j0 = blockIdx.x * 32;
    __shared__ float At[HEADS * CH * CH];
    __shared__ float Ms[32][201];
    __shared__ float Ws[32][33];
    const int t = threadIdx.x;

    for (int idx = t; idx < HEADS * CH * CH; idx += 256)
        At[idx] = g_attn[b * HEADS * CH * CH + idx];
    __syncthreads();

    for (int idx = t; idx < 32 * 192; idx += 256) {
        const int mi = idx / 192, k = idx % 192;
        const int h = k / CH, d = k % CH;
        const float* wrow = wout + (i0 + mi) * CCH + h * CH;
        const float* acol = At + h * 576 + d;
        float s = 0.f;
#pragma unroll
        for (int c = 0; c < CH; c++) s = fmaf(wrow[c], acol[c * CH], s);
        Ms[mi][k] = s;
    }
    __syncthreads();

    const int tx = t % 32, ty = t / 32;
    float acc[4] = {0.f, 0.f, 0.f, 0.f};
#pragma unroll 1
    for (int k0 = 0; k0 < CCH; k0 += 32) {
        const int r0 = t / 32, kk = t % 32;
#pragma unroll
        for (int rr = 0; rr < 32; rr += 8)
            Ws[r0 + rr][kk] = wqkv[(2 * CCH + k0 + r0 + rr) * CCH + j0 + kk];
        __syncthreads();
#pragma unroll
        for (int k2 = 0; k2 < 32; k2++) {
            const float bv = Ws[k2][tx];
#pragma unroll
            for (int u = 0; u < 4; u++)
                acc[u] = fmaf(Ms[ty + 8 * u][k0 + k2], bv, acc[u]);
        }
        __syncthreads();
    }
#pragma unroll
    for (int u = 0; u < 4; u++)
        g_Ph[b * CCH * CCH + (i0 + ty + 8 * u) * CCH + j0 + tx] = __float2half(acc[u]);
}

// =====================================================================
// Kernel 5: Y = P @ X via cp.async + ldmatrix. grid (3, 512, BATCH).
// =====================================================================
__global__ __launch_bounds__(256) void y_h2(float* __restrict__ Y) {
    const int b  = blockIdx.z;
    const int i0 = blockIdx.x * 64;
    const int n0 = blockIdx.y * 128;

    __shared__ __align__(16) __half Ps[64][200];
    __shared__ __align__(16) __half Xs[2][32][136];
    const uint32_t sbP = s2u(Ps), sbX = s2u(Xs);

    const int t = threadIdx.x, lane = t & 31, wid = t >> 5;
    const int g = lane >> 2, tg = lane & 3;
    const int lr = lane & 15, lu = lane >> 4;
    const int lb7 = lane & 7, lb8 = (lane >> 3) & 1, lb16 = lane >> 4;
    const int wm = (wid & 1) * 32, wn = (wid >> 1) * 32;

    const __half* Pbh = g_Ph + b * CCH * CCH;
    const __half* Xb = g_Xh + (size_t)b * CCH * NPIX;

#pragma unroll
    for (int i = 0; i < 6; i++) {
        const int idx = t + i * 256;
        const int r = idx / 24, c16 = idx % 24;
        *(uint4*)&Ps[r][c16 * 8] = *(const uint4*)(Pbh + (i0 + r) * CCH + c16 * 8);
    }

    const int xr = t >> 3, xu = (t & 7) * 2;
    const __half* srcX = Xb + (size_t)xr * NPIX + n0 + xu * 8;
    const uint32_t dX = sbX + xr * 272 + xu * 16;
    CPA16(dX, srcX);
    CPA16(dX + 16, srcX + 8);
    CPCOMMIT();

    float acc[2][4][4];
#pragma unroll
    for (int mi = 0; mi < 2; mi++)
#pragma unroll
        for (int nj = 0; nj < 4; nj++)
#pragma unroll
            for (int u = 0; u < 4; u++) acc[mi][nj][u] = 0.f;

    int buf = 0;
#pragma unroll 1
    for (int kt = 0; kt < 6; kt++) {
        if (kt + 1 < 6) {
            const uint32_t bo = (buf ^ 1) * 8704;
            const __half* s2 = srcX + (size_t)(kt + 1) * 32 * NPIX;
            CPA16(dX + bo, s2);
            CPA16(dX + bo + 16, s2 + 8);
            CPCOMMIT();
            CPWAIT(1);
        } else {
            CPWAIT(0);
        }
        __syncthreads();

        const uint32_t bo = buf * 8704;
#pragma unroll
        for (int kk = 0; kk < 32; kk += 16) {
            const int ku = kt * 4 + (kk >> 3);
            unsigned af[2][4], bf[4][2], tmp[4];
#pragma unroll
            for (int mi = 0; mi < 2; mi++)
                ldm_x4(af[mi], sbP + (wm + mi * 16 + lr) * 400 + (ku + lu) * 16);
            {
                const int rowb = kk + lb7 + lb8 * 8;
                const int un = (wn >> 3) + lb16;
                ldm_x4_t(tmp, sbX + bo + rowb * 272 + un * 16);
                bf[0][0] = tmp[0]; bf[0][1] = tmp[1];
                bf[1][0] = tmp[2]; bf[1][1] = tmp[3];
                ldm_x4_t(tmp, sbX + bo + rowb * 272 + (un + 2) * 16);
                bf[2][0] = tmp[0]; bf[2][1] = tmp[1];
                bf[3][0] = tmp[2]; bf[3][1] = tmp[3];
            }
#pragma unroll
            for (int mi = 0; mi < 2; mi++)
#pragma unroll
                for (int nj = 0; nj < 4; nj++)
                    mma_h(acc[mi][nj], af[mi], bf[nj][0], bf[nj][1]);
        }
        __syncthreads();
        buf ^= 1;
    }

    float* Yb = Y + (size_t)b * CCH * NPIX;
#pragma unroll
    for (int mi = 0; mi < 2; mi++)
#pragma unroll
        for (int nj = 0; nj < 4; nj++) {
            const int row = i0 + wm + mi * 16 + g;
            const int col = n0 + wn + nj * 8 + 2 * tg;
            *(float2*)&Yb[(size_t)row * NPIX + col]       = make_float2(acc[mi][nj][0], acc[mi][nj][1]);
            *(float2*)&Yb[(size_t)(row + 8) * NPIX + col] = make_float2(acc[mi][nj][2], acc[mi][nj][3]);
        }
}

// =====================================================================
// Launch
// =====================================================================
extern "C" void kernel_launch(void* const* d_in, const int* in_sizes, int n_in,
                              void* d_out, int out_size) {
    const float* x    = (const float*)d_in[0];
    const float* wqkv = (const float*)d_in[1];
    const float* wout = (const float*)d_in[2];
    const float* temp = (const float*)d_in[3];
    float* y          = (float*)d_out;
    (void)in_sizes; (void)n_in; (void)out_size;

    static bool attr_set = false;
    if (!attr_set) {
        cudaFuncSetAttribute(gram_f, cudaFuncAttributeMaxDynamicSharedMemorySize, GF_SMEM);
        cudaFuncSetAttribute(attn5, cudaFuncAttributeMaxDynamicSharedMemorySize,
                             (int)ATTN5_SMEM);
        attr_set = true;
    }

    gram_f<<<dim3(GSPLIT, BATCH), 256, GF_SMEM>>>(x);
    gram_reduce6<<<192, 256>>>();
    qk_kernel<<<dim3(12, 3, BATCH), 256>>>(wqkv);
    attn5<<<dim3(HEADS, BATCH), 768, ATTN5_SMEM>>>(wqkv, temp);
    mp_kernel<<<dim3(6, 6, BATCH), 256>>>(wout, wqkv);
    y_h2<<<dim3(3, 512, BATCH), 256>>>(y);
}